// round 12
// baseline (speedup 1.0000x reference)
#include <cuda_runtime.h>
#include <cstdint>

// Problem dims (fixed by reference)
#define BB 256
#define TT 1024
#define DD 64
#define HH 128
#define NB 8      // batches per scan CTA (MMA N dimension)

typedef unsigned long long ull;

static constexpr size_t BT  = (size_t)BB * TT;        // 262144
static constexpr size_t BTH = (size_t)BB * TT * HH;   // 33554432

// Interleaved scratch: (gate_x_K, tanh(gate_x_z)) per (b,t,h). No cudaMalloc.
// Padded 4 rows so the scan prefetch (distance 2) is unconditional.
__device__ float2 g_gz[BTH + 4 * HH];

// ---- packed f32x2 helpers (proj kernel) ----
__device__ __forceinline__ void fma2(ull& acc, ull a, ull b) {
    asm("fma.rn.f32x2 %0, %1, %2, %0;" : "+l"(acc) : "l"(a), "l"(b));
}
__device__ __forceinline__ void add2(ull& a, ull b) {
    asm("add.rn.f32x2 %0, %0, %1;" : "+l"(a) : "l"(b));
}
__device__ __forceinline__ float2 unpk(ull v) {
    float2 f;
    asm("mov.b64 {%0, %1}, %2;" : "=f"(f.x), "=f"(f.y) : "l"(v));
    return f;
}
// Hardware tanh (MUFU.TANH)
__device__ __forceinline__ float tanh_hw(float x) {
    float r;
    asm("tanh.approx.f32 %0, %1;" : "=f"(r) : "f"(x));
    return r;
}
__device__ __forceinline__ float sigmoid_hw(float x) {
    return fmaf(0.5f, tanh_hw(0.5f * x), 0.5f);
}
// Round f32 -> tf32 (result has low 13 mantissa bits zero), returned as f32 bits.
__device__ __forceinline__ uint32_t to_tf32(float x) {
    uint32_t u;
    asm("cvt.rn.tf32.f32 %0, %1;" : "=r"(u) : "f"(x));
    return u;
}

// ---------------------------------------------------------------------------
// Kernel 1: input projections (unchanged; ~225us)
// ---------------------------------------------------------------------------
__global__ void __launch_bounds__(128)
proj_kernel(const float* __restrict__ x,
            const float* __restrict__ WxK, const float* __restrict__ bxK,
            const float* __restrict__ Wxz, const float* __restrict__ bxz)
{
    constexpr int ROWS = 64;
    __shared__ __align__(16) float xs[ROWS * DD];   // 16 KB

    const int i = threadIdx.x;
    const size_t row0 = (size_t)blockIdx.x * ROWS;

    const float4* xg  = (const float4*)(x + row0 * DD);
    float4*       xs4 = (float4*)xs;
#pragma unroll
    for (int k = 0; k < 8; k++) xs4[i + 128 * k] = xg[i + 128 * k];

    ulonglong2 wK[16], wz[16];
    {
        const ulonglong2* wKr = (const ulonglong2*)(WxK + i * DD);
        const ulonglong2* wzr = (const ulonglong2*)(Wxz + i * DD);
#pragma unroll
        for (int m = 0; m < 16; m++) { wK[m] = wKr[m]; wz[m] = wzr[m]; }
    }
    const float bK = bxK[i];
    const float bz = bxz[i];
    __syncthreads();

    for (int r = 0; r < ROWS; r += 2) {
        const ulonglong2* xr0 = (const ulonglong2*)(xs + r * DD);
        const ulonglong2* xr1 = (const ulonglong2*)(xs + (r + 1) * DD);
        ull aK0 = 0, aK1 = 0, az0 = 0, az1 = 0;
        ull cK0 = 0, cK1 = 0, cz0 = 0, cz1 = 0;
#pragma unroll
        for (int m = 0; m < 16; m++) {
            ulonglong2 xv0 = xr0[m];
            ulonglong2 xv1 = xr1[m];
            fma2(aK0, wK[m].x, xv0.x); fma2(aK1, wK[m].y, xv0.y);
            fma2(az0, wz[m].x, xv0.x); fma2(az1, wz[m].y, xv0.y);
            fma2(cK0, wK[m].x, xv1.x); fma2(cK1, wK[m].y, xv1.y);
            fma2(cz0, wz[m].x, xv1.x); fma2(cz1, wz[m].y, xv1.y);
        }
        add2(aK0, aK1); add2(az0, az1); add2(cK0, cK1); add2(cz0, cz1);
        float2 k0 = unpk(aK0), z0 = unpk(az0);
        float2 k1 = unpk(cK0), z1 = unpk(cz0);

        size_t n0 = (row0 + r) * HH + i;
        size_t n1 = n0 + HH;
        g_gz[n0] = make_float2(k0.x + k0.y + bK, tanh_hw(z0.x + z0.y + bz));
        g_gz[n1] = make_float2(k1.x + k1.y + bK, tanh_hw(z1.x + z1.y + bz));
    }
}

// ---------------------------------------------------------------------------
// Kernel 2: tensor-core scan. One CTA (256 thr = 8 warps) handles NB=8
// batches; grid = 32. Per step: C[128x8] = W[128x128] @ H[128x8] via
// mma.sync.m16n8k8.tf32 (warp w owns output rows 16w..16w+15; A = weights
// resident in registers across ALL steps). H stage in smem holds
// tf32-rounded h (rounded once at store); h itself stays fp32 in the
// recurrence. B loads are conflict-free distinct-address LDS.32.
//
// mma.m16n8k8 fragment maps (g = lane>>2, tig = lane&3):
//   A: a0=(g,tig) a1=(g+8,tig) a2=(g,tig+4) a3=(g+8,tig+4)   [row-major]
//   B: b0=(k=tig, n=g) b1=(k=tig+4, n=g)                      [col-major]
//   C: c0=(g,2tig) c1=(g,2tig+1) c2=(g+8,2tig) c3=(g+8,2tig+1)
// ---------------------------------------------------------------------------
__device__ __forceinline__ void mma_tf32(float c[4], const uint32_t a[4],
                                         uint32_t b0, uint32_t b1) {
    asm volatile(
        "mma.sync.aligned.m16n8k8.row.col.f32.tf32.tf32.f32 "
        "{%0,%1,%2,%3}, {%4,%5,%6,%7}, {%8,%9}, {%0,%1,%2,%3};"
        : "+f"(c[0]), "+f"(c[1]), "+f"(c[2]), "+f"(c[3])
        : "r"(a[0]), "r"(a[1]), "r"(a[2]), "r"(a[3]), "r"(b0), "r"(b1));
}

__global__ void __launch_bounds__(256, 1)
scan_kernel(const float* __restrict__ WhK, const float* __restrict__ bhK,
            float* __restrict__ out, int dup)
{
    // [buf][n][k] with 132-float rows: bank(n*132+k) = (4n+k)%32 ->
    // B loads and h stores are conflict-free.
    __shared__ float hs[2][NB][132];

    const int tid  = threadIdx.x;
    const int w    = tid >> 5;
    const int lane = tid & 31;
    const int g    = lane >> 2;
    const int tig  = lane & 3;
    const int b0blk = blockIdx.x * NB;

    // A fragments: W rows (16w+g, 16w+g+8), all 16 k-chunks, tf32.
    uint32_t A[16][4];
    const int i0 = 16 * w + g;
    const int i1 = i0 + 8;
#pragma unroll
    for (int kc = 0; kc < 16; kc++) {
        int kb = 8 * kc + tig;
        A[kc][0] = to_tf32(WhK[i0 * HH + kb]);
        A[kc][1] = to_tf32(WhK[i1 * HH + kb]);
        A[kc][2] = to_tf32(WhK[i0 * HH + kb + 4]);
        A[kc][3] = to_tf32(WhK[i1 * HH + kb + 4]);
    }
    const float bh0 = bhK[i0];
    const float bh1 = bhK[i1];

    // This thread's 4 C elements: (i0,n0),(i0,n1),(i1,n0),(i1,n1)
    const int n0 = 2 * tig, n1 = n0 + 1;
    const int ii[4] = { i0, i0, i1, i1 };
    const int nn[4] = { n0, n1, n0, n1 };

    const float2* gp[4];
    float* op[4];
    float* oq[4];
    float h[4];
    float2 gza[4], gzb[4];
#pragma unroll
    for (int j = 0; j < 4; j++) {
        size_t base = ((size_t)(b0blk + nn[j]) * TT) * HH + ii[j];
        gp[j] = g_gz + base;
        op[j] = out + base;
        oq[j] = op[j] + BTH;
        h[j] = 0.0f;
        gza[j] = gp[j][0];
        gzb[j] = gp[j][HH];
        gp[j] += 2 * HH;
    }

    // zero stage buffer 0
    for (int idx = tid; idx < NB * 132; idx += 256)
        (&hs[0][0][0])[idx] = 0.0f;
    __syncthreads();

    int cur = 0;
    for (int t = 0; t < TT; t++) {
        const float* hb = &hs[cur][0][0];
        float c[4][4] = {{0,0,0,0},{0,0,0,0},{0,0,0,0},{0,0,0,0}};
#pragma unroll
        for (int kc = 0; kc < 16; kc++) {
            // B: distinct-address LDS.32, bank = (lane + 8kc)%32 -> no conflict
            uint32_t bb0 = __float_as_uint(hb[g * 132 + 8 * kc + tig]);
            uint32_t bb1 = __float_as_uint(hb[g * 132 + 8 * kc + tig + 4]);
            mma_tf32(c[kc & 3], A[kc], bb0, bb1);
        }
        float s0 = c[0][0] + c[1][0] + c[2][0] + c[3][0] + bh0;
        float s1 = c[0][1] + c[1][1] + c[2][1] + c[3][1] + bh0;
        float s2 = c[0][2] + c[1][2] + c[2][2] + c[3][2] + bh1;
        float s3 = c[0][3] + c[1][3] + c[2][3] + c[3][3] + bh1;
        float sj[4] = { s0, s1, s2, s3 };

#pragma unroll
        for (int j = 0; j < 4; j++) {
            float kg = sigmoid_hw(gza[j].x + sj[j]);
            h[j] = tanh_hw(fmaf(kg, gza[j].y - h[j], h[j]));
            gza[j] = gzb[j];
            gzb[j] = *gp[j];           // unconditional: scratch padded
            gp[j] += HH;
            op[j][0] = h[j];
            if (dup) oq[j][0] = h[j];
            op[j] += HH; oq[j] += HH;
        }

        // store tf32-rounded h for next step's B operand (conflict-free)
        int nxt = cur ^ 1;
        hs[nxt][n0][i0] = __uint_as_float(to_tf32(h[0]));
        hs[nxt][n1][i0] = __uint_as_float(to_tf32(h[1]));
        hs[nxt][n0][i1] = __uint_as_float(to_tf32(h[2]));
        hs[nxt][n1][i1] = __uint_as_float(to_tf32(h[3]));
        __syncthreads();
        cur = nxt;
    }
}

// ---------------------------------------------------------------------------
extern "C" void kernel_launch(void* const* d_in, const int* in_sizes, int n_in,
                              void* d_out, int out_size)
{
    const float* x   = (const float*)d_in[0];
    const float* WxK = (const float*)d_in[1];
    const float* bxK = (const float*)d_in[2];
    const float* Wxz = (const float*)d_in[3];
    const float* bxz = (const float*)d_in[4];
    const float* WhK = (const float*)d_in[5];
    const float* bhK = (const float*)d_in[6];
    float* out = (float*)d_out;

    proj_kernel<<<(int)(BT / 64), 128>>>(x, WxK, bxK, Wxz, bxz);

    const int dup = ((size_t)out_size >= 2 * BTH) ? 1 : 0;
    scan_kernel<<<BB / NB, 256>>>(WhK, bhK, out, dup);
}